// round 1
// baseline (speedup 1.0000x reference)
#include <cuda_runtime.h>
#include <cuda_bf16.h>

// ContrastiveLoss: loss = -log(num/(den+1e-9)+1e-10)
//   S[i,j] = exp((x[i] . y_sel[j]) / 0.3),  y_sel = y.reshape(4096,128)
//   pos(i,j) = (track_idxs[i] == (j % 512))   [y_idxs = tile(arange(512), 8)]
//   num = sum of S over pos, den = sum over !pos
//
// Shapes: x [32768,128] f32, track_idxs [32768] i32, y [512,8,128] f32, out [1] f32.

#define BM 128
#define BN 128
#define BK 32
#define PAD 4
#define LDS_STRIDE (BM + PAD) /* 132 floats; row stride 528B = 16B-aligned */

// per-CTA partials: (pos_sum, all_sum). 256 row tiles * 32 col tiles = 8192.
__device__ float2 g_partials[8192];

__device__ __forceinline__ unsigned long long pack2(float lo, float hi) {
    unsigned long long r;
    asm("mov.b64 %0, {%1, %2};" : "=l"(r) : "f"(lo), "f"(hi));
    return r;
}

__device__ __forceinline__ unsigned long long ffma2(unsigned long long a,
                                                    unsigned long long b,
                                                    unsigned long long c) {
    unsigned long long d;
    asm("fma.rn.f32x2 %0, %1, %2, %3;" : "=l"(d) : "l"(a), "l"(b), "l"(c));
    return d;
}

__device__ __forceinline__ void unpack2(unsigned long long v, float& lo, float& hi) {
    asm("mov.b64 {%0, %1}, %2;" : "=f"(lo), "=f"(hi) : "l"(v));
}

// exp(s/0.3) = 2^(s * log2(e)/0.3), |s| <= ~1 so exponent in [-4.81, 4.81].
// Degree-5 Taylor for 2^f on f in [-0.5, 0.5]: max rel err ~2.4e-6.
// Runs entirely on FMA/ALU pipes (no MUFU).
__device__ __forceinline__ float fast_exp_scaled(float s) {
    float z = s * 4.80898346962988f;          // log2(e)/0.3
    float t = z + 12582912.0f;                // 2^23 + 2^22 round-to-nearest magic
    float nf = t - 12582912.0f;
    float f = z - nf;                         // f in [-0.5, 0.5]
    float p = 1.3333558146e-3f;               // ln2^5/120
    p = fmaf(p, f, 9.6181291076e-3f);         // ln2^4/24
    p = fmaf(p, f, 5.5504108664e-2f);         // ln2^3/6
    p = fmaf(p, f, 2.4022650696e-1f);         // ln2^2/2
    p = fmaf(p, f, 6.9314718056e-1f);         // ln2
    p = fmaf(p, f, 1.0f);
    int n = __float_as_int(t) - 0x4B400000;   // integer part of z
    float sc = __int_as_float((n + 127) << 23);
    return p * sc;
}

__global__ __launch_bounds__(256)
void cl_main_kernel(const float* __restrict__ x, const int* __restrict__ trk,
                    const float* __restrict__ y, int nColTiles) {
    __shared__ float As[BK * LDS_STRIDE];
    __shared__ float Bs[BK * LDS_STRIDE];
    __shared__ int trk_s[BM];
    __shared__ float red[16];

    const int tid = threadIdx.x;
    const int bx = blockIdx.x;  // y_sel column tile
    const int by = blockIdx.y;  // x row tile
    const int tx = tid & 15;
    const int ty = tid >> 4;

    if (tid < BM) trk_s[tid] = trk[by * BM + tid];

    // row stride of x / y_sel is 128 floats = 32 float4
    const float4* xg = (const float4*)x + (size_t)by * BM * 32;
    const float4* yg = (const float4*)y + (size_t)bx * BN * 32;

    unsigned long long acc[8][4];
#pragma unroll
    for (int i = 0; i < 8; i++)
#pragma unroll
        for (int j = 0; j < 4; j++) acc[i][j] = 0ull;

#pragma unroll
    for (int kk = 0; kk < 4; kk++) {
        __syncthreads();
        // Stage a BMx32 chunk of x and a BNx32 chunk of y_sel, k-major.
#pragma unroll
        for (int s = 0; s < 4; s++) {
            int e = tid + s * 256;
            int row = e >> 3;      // 8 float4 per row-chunk
            int q = e & 7;
            float4 v = xg[row * 32 + kk * 8 + q];
            float4 w = yg[row * 32 + kk * 8 + q];
            int kb = q * 4;
            As[(kb + 0) * LDS_STRIDE + row] = v.x;
            As[(kb + 1) * LDS_STRIDE + row] = v.y;
            As[(kb + 2) * LDS_STRIDE + row] = v.z;
            As[(kb + 3) * LDS_STRIDE + row] = v.w;
            Bs[(kb + 0) * LDS_STRIDE + row] = w.x;
            Bs[(kb + 1) * LDS_STRIDE + row] = w.y;
            Bs[(kb + 2) * LDS_STRIDE + row] = w.z;
            Bs[(kb + 3) * LDS_STRIDE + row] = w.w;
        }
        __syncthreads();

#pragma unroll
        for (int k = 0; k < BK; k++) {
            const float4 a0 = *(const float4*)&As[k * LDS_STRIDE + ty * 8];
            const float4 a1 = *(const float4*)&As[k * LDS_STRIDE + ty * 8 + 4];
            const float4 b0 = *(const float4*)&Bs[k * LDS_STRIDE + tx * 8];
            const float4 b1 = *(const float4*)&Bs[k * LDS_STRIDE + tx * 8 + 4];
            unsigned long long bb[4];
            bb[0] = pack2(b0.x, b0.y);
            bb[1] = pack2(b0.z, b0.w);
            bb[2] = pack2(b1.x, b1.y);
            bb[3] = pack2(b1.z, b1.w);
            float av[8] = {a0.x, a0.y, a0.z, a0.w, a1.x, a1.y, a1.z, a1.w};
#pragma unroll
            for (int i = 0; i < 8; i++) {
                unsigned long long aa = pack2(av[i], av[i]);
#pragma unroll
                for (int j = 0; j < 4; j++) acc[i][j] = ffma2(aa, bb[j], acc[i][j]);
            }
        }
    }

    // Epilogue: exp + masked accumulate.
    float s_all = 0.0f, s_pos = 0.0f;
    const int colbase = bx * BN + tx * 8;
#pragma unroll
    for (int i = 0; i < 8; i++) {
        int t = trk_s[ty * 8 + i];
#pragma unroll
        for (int j = 0; j < 4; j++) {
            float lo, hi;
            unpack2(acc[i][j], lo, hi);
            float e0 = fast_exp_scaled(lo);
            float e1 = fast_exp_scaled(hi);
            s_all += e0 + e1;
            int c0 = (colbase + j * 2 + 0) & 511;
            int c1 = (colbase + j * 2 + 1) & 511;
            if (t == c0) s_pos += e0;
            if (t == c1) s_pos += e1;
        }
    }

    // Block reduce (deterministic, no atomics).
#pragma unroll
    for (int o = 16; o > 0; o >>= 1) {
        s_all += __shfl_down_sync(0xffffffffu, s_all, o);
        s_pos += __shfl_down_sync(0xffffffffu, s_pos, o);
    }
    const int wid = tid >> 5, lane = tid & 31;
    if (lane == 0) { red[wid] = s_all; red[wid + 8] = s_pos; }
    __syncthreads();
    if (tid == 0) {
        float a = 0.0f, p = 0.0f;
#pragma unroll
        for (int w = 0; w < 8; w++) { a += red[w]; p += red[w + 8]; }
        g_partials[by * nColTiles + bx] = make_float2(p, a);
    }
}

__global__ void cl_finalize_kernel(float* __restrict__ out, int nb) {
    __shared__ double red[16];
    const int tid = threadIdx.x;
    double a = 0.0, p = 0.0;
    for (int i = tid; i < nb; i += 256) {
        float2 v = g_partials[i];
        p += (double)v.x;
        a += (double)v.y;
    }
#pragma unroll
    for (int o = 16; o > 0; o >>= 1) {
        a += __shfl_down_sync(0xffffffffu, a, o);
        p += __shfl_down_sync(0xffffffffu, p, o);
    }
    const int wid = tid >> 5, lane = tid & 31;
    if (lane == 0) { red[wid] = a; red[wid + 8] = p; }
    __syncthreads();
    if (tid == 0) {
        double aa = 0.0, pp = 0.0;
        for (int w = 0; w < 8; w++) { aa += red[w]; pp += red[w + 8]; }
        double den = aa - pp;
        double r = pp / (den + 1e-9) + 1e-10;
        out[0] = (float)(-log(r));
    }
}

extern "C" void kernel_launch(void* const* d_in, const int* in_sizes, int n_in,
                              void* d_out, int out_size) {
    const float* x = (const float*)d_in[0];        // [N,128]
    const int* trk = (const int*)d_in[1];          // [N]
    const float* y = (const float*)d_in[2];        // [512,8,128] -> y_sel [4096,128]

    const int N = in_sizes[1];                     // 32768
    const int TQ = in_sizes[2] / 128;              // 4096
    const int rowTiles = N / BM;                   // 256
    const int colTiles = TQ / BN;                  // 32

    dim3 grid(colTiles, rowTiles);
    cl_main_kernel<<<grid, 256>>>(x, trk, y, colTiles);
    cl_finalize_kernel<<<1, 256>>>((float*)d_out, rowTiles * colTiles);
}

// round 4
// speedup vs baseline: 5.5590x; 5.5590x over previous
#include <cuda_runtime.h>
#include <cuda_bf16.h>
#include <cstdint>

// ContrastiveLoss: loss = -log(num/(den+1e-9)+1e-10)
//   S[i,j] = exp((x[i] . y_sel[j]) / 0.3),  y_sel = y.reshape(4096,128)
//   pos(i,j) = (track_idxs[i] == (j % 512))
// x [32768,128] f32, track_idxs [32768] i32, y [512,8,128] f32, out [1] f32.
//
// Portable-PTX tensor path (harness targets bare sm_100, no 'a' features):
// bf16 mma.sync.m16n8k16 GEMM, 128x128 CTA tile, fused packed-f32x2 exp +
// masked reduction epilogue, deterministic per-CTA partials.

#define NROWS 32768
#define NCOLS 4096
#define NTILE_R (NROWS / 128)   /* 256 */
#define NTILE_C (NCOLS / 128)   /* 32  */

__device__ __nv_bfloat16 g_xb[NROWS * 128];
__device__ __nv_bfloat16 g_yb[NCOLS * 128];
__device__ float2 g_partials[NTILE_R * NTILE_C];

// ---------------- helpers ----------------
__device__ __forceinline__ uint32_t smem_to_u32(const void* p) {
    uint32_t a;
    asm("{ .reg .u64 t; cvta.to.shared.u64 t, %1; cvt.u32.u64 %0, t; }"
        : "=r"(a) : "l"(p));
    return a;
}

__device__ __forceinline__ void cp_async16(uint32_t saddr, const void* gaddr) {
    asm volatile("cp.async.cg.shared.global [%0], [%1], 16;"
                 :: "r"(saddr), "l"(gaddr) : "memory");
}
__device__ __forceinline__ void cp_async_wait_all() {
    asm volatile("cp.async.commit_group;\n\tcp.async.wait_group 0;" ::: "memory");
}

__device__ __forceinline__ void ldsm_x4(uint32_t& r0, uint32_t& r1, uint32_t& r2,
                                        uint32_t& r3, uint32_t addr) {
    asm volatile("ldmatrix.sync.aligned.m8n8.x4.shared.b16 {%0,%1,%2,%3}, [%4];"
                 : "=r"(r0), "=r"(r1), "=r"(r2), "=r"(r3) : "r"(addr));
}

__device__ __forceinline__ void mma16816(float& d0, float& d1, float& d2, float& d3,
                                         uint32_t a0, uint32_t a1, uint32_t a2,
                                         uint32_t a3, uint32_t b0, uint32_t b1) {
    asm volatile(
        "mma.sync.aligned.m16n8k16.row.col.f32.bf16.bf16.f32 "
        "{%0,%1,%2,%3}, {%4,%5,%6,%7}, {%8,%9}, {%0,%1,%2,%3};"
        : "+f"(d0), "+f"(d1), "+f"(d2), "+f"(d3)
        : "r"(a0), "r"(a1), "r"(a2), "r"(a3), "r"(b0), "r"(b1));
}

// packed f32x2 ops (Blackwell f32x2 pipe)
__device__ __forceinline__ unsigned long long pk2(float lo, float hi) {
    unsigned long long r;
    asm("mov.b64 %0, {%1, %2};" : "=l"(r) : "f"(lo), "f"(hi));
    return r;
}
__device__ __forceinline__ void upk2(unsigned long long v, float& lo, float& hi) {
    asm("mov.b64 {%0, %1}, %2;" : "=f"(lo), "=f"(hi) : "l"(v));
}
__device__ __forceinline__ void upk2u(unsigned long long v, uint32_t& lo, uint32_t& hi) {
    asm("mov.b64 {%0, %1}, %2;" : "=r"(lo), "=r"(hi) : "l"(v));
}
__device__ __forceinline__ unsigned long long pk2u(uint32_t lo, uint32_t hi) {
    unsigned long long r;
    asm("mov.b64 %0, {%1, %2};" : "=l"(r) : "r"(lo), "r"(hi));
    return r;
}
__device__ __forceinline__ unsigned long long addx2(unsigned long long a, unsigned long long b) {
    unsigned long long d;
    asm("add.rn.f32x2 %0, %1, %2;" : "=l"(d) : "l"(a), "l"(b));
    return d;
}
__device__ __forceinline__ unsigned long long mulx2(unsigned long long a, unsigned long long b) {
    unsigned long long d;
    asm("mul.rn.f32x2 %0, %1, %2;" : "=l"(d) : "l"(a), "l"(b));
    return d;
}
__device__ __forceinline__ unsigned long long fmax2(unsigned long long a, unsigned long long b,
                                                    unsigned long long c) {
    unsigned long long d;
    asm("fma.rn.f32x2 %0, %1, %2, %3;" : "=l"(d) : "l"(a), "l"(b), "l"(c));
    return d;
}

// SW128-style blocked-atom smem layout: atom = 8 rows x 64 bf16 (1024B);
// 16 atom-rows x 2 atom-cols; conflict-free for ldmatrix + 16B stores.
__device__ __forceinline__ uint32_t tile_off(int row, int col8) {
    uint32_t atom = (uint32_t)((row >> 3) + ((col8 >> 6) << 4));
    uint32_t boff = atom * 1024u + (uint32_t)(row & 7) * 128u + (uint32_t)(col8 & 63) * 2u;
    return boff ^ ((boff >> 3) & 0x70u);
}

#define OFF_TRK  0       /* 128 ints = 512B */
#define OFF_RED  512     /* 16 floats */
#define OFF_A    1024    /* 32KB */
#define OFF_B    33792   /* 32KB */
#define SMEM_TOTAL 66560

// ---------------- kernels ----------------
__global__ __launch_bounds__(256)
void cvt_bf16_kernel(const float* __restrict__ in, __nv_bfloat16* __restrict__ out, int n4) {
    int i = blockIdx.x * blockDim.x + threadIdx.x;
    if (i < n4) {
        float4 v = ((const float4*)in)[i];
        __nv_bfloat162 a = __floats2bfloat162_rn(v.x, v.y);
        __nv_bfloat162 b = __floats2bfloat162_rn(v.z, v.w);
        uint2 o;
        o.x = *(uint32_t*)&a;
        o.y = *(uint32_t*)&b;
        ((uint2*)out)[i] = o;
    }
}

__global__ __launch_bounds__(256)
void cl_mma_kernel(const int* __restrict__ trk) {
    extern __shared__ char smem[];
    const uint32_t sb = smem_to_u32(smem);
    const int tid = threadIdx.x;
    const int wid = tid >> 5, lane = tid & 31;
    const int bx = blockIdx.x;   // col tile 0..31
    const int by = blockIdx.y;   // row tile 0..255

    const int wrow = wid & 3;    // 4 row groups x 32 rows
    const int wcol = wid >> 2;   // 2 col groups x 64 cols

    if (tid < 128) ((int*)(smem + OFF_TRK))[tid] = trk[by * 128 + tid];

    // Stage A (x tile) and B (y tile): 2048 x 16B each, cp.async.
    {
        const char* xg = (const char*)g_xb + (size_t)by * 128 * 256;
        const char* yg = (const char*)g_yb + (size_t)bx * 128 * 256;
#pragma unroll
        for (int i = 0; i < 8; i++) {
            int idx = tid + i * 256;
            int row = idx >> 4;
            int col8 = (idx & 15) << 3;
            uint32_t so = tile_off(row, col8);
            cp_async16(sb + OFF_A + so, xg + row * 256 + col8 * 2);
            cp_async16(sb + OFF_B + so, yg + row * 256 + col8 * 2);
        }
    }
    cp_async_wait_all();
    __syncthreads();

    // ---- mainloop: K=128 in 8 k-steps of 16 ----
    float acc[2][8][4];
#pragma unroll
    for (int mi = 0; mi < 2; mi++)
#pragma unroll
        for (int ni = 0; ni < 8; ni++)
#pragma unroll
            for (int q = 0; q < 4; q++) acc[mi][ni][q] = 0.0f;

    const int a_row = wrow * 32 + (lane & 15);        // + mi*16
    const int a_k8 = (lane >> 4) << 3;
    const int b_row = wcol * 64 + ((lane >> 4) << 3) + (lane & 7);  // + nq*16
    const int b_k8 = ((lane >> 3) & 1) << 3;

#pragma unroll
    for (int ks = 0; ks < 8; ks++) {
        const int kc = ks * 16;
        uint32_t a[2][4];
#pragma unroll
        for (int mi = 0; mi < 2; mi++)
            ldsm_x4(a[mi][0], a[mi][1], a[mi][2], a[mi][3],
                    sb + OFF_A + tile_off(a_row + mi * 16, kc + a_k8));
        uint32_t b[4][4];
#pragma unroll
        for (int nq = 0; nq < 4; nq++)
            ldsm_x4(b[nq][0], b[nq][1], b[nq][2], b[nq][3],
                    sb + OFF_B + tile_off(b_row + nq * 16, kc + b_k8));
#pragma unroll
        for (int mi = 0; mi < 2; mi++)
#pragma unroll
            for (int ni = 0; ni < 8; ni++) {
                uint32_t b0 = b[ni >> 1][(ni & 1) * 2];
                uint32_t b1 = b[ni >> 1][(ni & 1) * 2 + 1];
                mma16816(acc[mi][ni][0], acc[mi][ni][1], acc[mi][ni][2], acc[mi][ni][3],
                         a[mi][0], a[mi][1], a[mi][2], a[mi][3], b0, b1);
            }
    }

    // ---- epilogue: packed exp + masked reduce ----
    const unsigned long long C2    = pk2(4.80898346962988f, 4.80898346962988f);
    const unsigned long long MAG2  = pk2(12582912.0f, 12582912.0f);
    const unsigned long long NMAG2 = pk2(-12582912.0f, -12582912.0f);
    const unsigned long long NONE2 = pk2(-1.0f, -1.0f);
    const unsigned long long ONE2  = pk2(1.0f, 1.0f);
    const unsigned long long P5    = pk2(1.3333558146e-3f, 1.3333558146e-3f);
    const unsigned long long P4    = pk2(9.6181291076e-3f, 9.6181291076e-3f);
    const unsigned long long P3    = pk2(5.5504108664e-2f, 5.5504108664e-2f);
    const unsigned long long P2    = pk2(2.4022650696e-1f, 2.4022650696e-1f);
    const unsigned long long P1    = pk2(6.9314718056e-1f, 6.9314718056e-1f);

    unsigned long long sall2 = 0ull;
    float spos = 0.0f;
    const int bxm = bx & 3;
    const int cbase = wcol * 64 + (lane & 3) * 2;
    const int* trk_s = (const int*)(smem + OFF_TRK);

#pragma unroll
    for (int mi = 0; mi < 2; mi++) {
        const int r0 = wrow * 32 + mi * 16 + (lane >> 2);
        const int t0 = trk_s[r0];
        const int t1 = trk_s[r0 + 8];
        const int pc0 = ((t0 >> 7) == bxm) ? (t0 & 127) : -1;
        const int pc1 = ((t1 >> 7) == bxm) ? (t1 & 127) : -1;
#pragma unroll
        for (int ni = 0; ni < 8; ni++) {
            const int c = cbase + ni * 8;
#pragma unroll
            for (int h = 0; h < 2; h++) {   // h=0: rows r0 (d0,d1); h=1: r0+8 (d2,d3)
                unsigned long long s2 = pk2(acc[mi][ni][2 * h], acc[mi][ni][2 * h + 1]);
                unsigned long long z  = mulx2(s2, C2);
                unsigned long long tt = addx2(z, MAG2);
                unsigned long long nf = addx2(tt, NMAG2);
                unsigned long long f  = fmax2(nf, NONE2, z);
                unsigned long long p  = fmax2(P5, f, P4);
                p = fmax2(p, f, P3);
                p = fmax2(p, f, P2);
                p = fmax2(p, f, P1);
                p = fmax2(p, f, ONE2);
                uint32_t tlo, thi;
                upk2u(tt, tlo, thi);
                uint32_t slo = (tlo + 0xB4C0007Fu) << 23;
                uint32_t shi = (thi + 0xB4C0007Fu) << 23;
                unsigned long long e2 = mulx2(p, pk2u(slo, shi));
                sall2 = addx2(sall2, e2);
                const int pc = h ? pc1 : pc0;
                if (pc >= 0 && ((pc | 1) == (c | 1))) {
                    float e0, e1;
                    upk2(e2, e0, e1);
                    spos += (pc == c) ? e0 : e1;
                }
            }
        }
    }

    float a0, a1;
    upk2(sall2, a0, a1);
    float sall = a0 + a1;

#pragma unroll
    for (int o = 16; o > 0; o >>= 1) {
        sall += __shfl_down_sync(0xffffffffu, sall, o);
        spos += __shfl_down_sync(0xffffffffu, spos, o);
    }
    float* red = (float*)(smem + OFF_RED);
    if (lane == 0) { red[wid] = sall; red[wid + 8] = spos; }
    __syncthreads();
    if (tid == 0) {
        float a = 0.0f, p = 0.0f;
#pragma unroll
        for (int w = 0; w < 8; w++) { a += red[w]; p += red[w + 8]; }
        g_partials[by * NTILE_C + bx] = make_float2(p, a);
    }
}

__global__ __launch_bounds__(256)
void cl_finalize_kernel(float* __restrict__ out, int nb) {
    __shared__ double red[16];
    const int tid = threadIdx.x;
    double a = 0.0, p = 0.0;
    for (int i = tid; i < nb; i += 256) {
        float2 v = g_partials[i];
        p += (double)v.x;
        a += (double)v.y;
    }
#pragma unroll
    for (int o = 16; o > 0; o >>= 1) {
        a += __shfl_down_sync(0xffffffffu, a, o);
        p += __shfl_down_sync(0xffffffffu, p, o);
    }
    const int wid = tid >> 5, lane = tid & 31;
    if (lane == 0) { red[wid] = a; red[wid + 8] = p; }
    __syncthreads();
    if (tid == 0) {
        double aa = 0.0, pp = 0.0;
        for (int w = 0; w < 8; w++) { aa += red[w]; pp += red[w + 8]; }
        double den = aa - pp;
        double r = pp / (den + 1e-9) + 1e-10;
        out[0] = (float)(-log(r));
    }
}

extern "C" void kernel_launch(void* const* d_in, const int* in_sizes, int n_in,
                              void* d_out, int out_size) {
    const float* x = (const float*)d_in[0];    // [32768,128]
    const int* trk = (const int*)d_in[1];      // [32768]
    const float* y = (const float*)d_in[2];    // [512,8,128]

    cudaFuncSetAttribute(cl_mma_kernel, cudaFuncAttributeMaxDynamicSharedMemorySize,
                         SMEM_TOTAL);

    __nv_bfloat16* xb;
    __nv_bfloat16* yb;
    cudaGetSymbolAddress((void**)&xb, g_xb);
    cudaGetSymbolAddress((void**)&yb, g_yb);

    const int xn4 = NROWS * 128 / 4;   // 1048576
    const int yn4 = NCOLS * 128 / 4;   // 131072
    cvt_bf16_kernel<<<(xn4 + 255) / 256, 256>>>(x, xb, xn4);
    cvt_bf16_kernel<<<(yn4 + 255) / 256, 256>>>(y, yb, yn4);

    dim3 grid(NTILE_C, NTILE_R);       // (32, 256)
    cl_mma_kernel<<<grid, 256, SMEM_TOTAL>>>(trk);

    cl_finalize_kernel<<<1, 256>>>((float*)d_out, NTILE_R * NTILE_C);
}